// round 1
// baseline (speedup 1.0000x reference)
#include <cuda_runtime.h>
#include <cstdint>
#include <cstddef>

#define Bb 32
#define Nn 1024
#define DIM 512
#define Hh 8
#define DHd 64
#define SCALE 0.125f

// Scratch (device globals: allocation-free per harness rules)
__device__ float g_Q[Bb*Hh*Nn*DHd];   // [b,h,n,d]
__device__ float g_K[Bb*Hh*Nn*DHd];
__device__ float g_V[Bb*Hh*Nn*DHd];
__device__ float g_O[Bb*Nn*Hh*DHd];   // [b,n,h*64+d]

__device__ __forceinline__ float tf32r(float x){
    unsigned r; asm("cvt.rna.tf32.f32 %0, %1;" : "=r"(r) : "f"(x));
    return __uint_as_float(r);
}
__device__ __forceinline__ unsigned fu(float x){ return __float_as_uint(x); }

// D += A(16x8,row) * B(8x8,col)  tf32
__device__ __forceinline__ void mma8(float* d, const unsigned* a, const unsigned* b){
    asm volatile(
        "mma.sync.aligned.m16n8k8.row.col.f32.tf32.tf32.f32 "
        "{%0,%1,%2,%3},{%4,%5,%6,%7},{%8,%9},{%0,%1,%2,%3};\n"
        : "+f"(d[0]), "+f"(d[1]), "+f"(d[2]), "+f"(d[3])
        : "r"(a[0]), "r"(a[1]), "r"(a[2]), "r"(a[3]), "r"(b[0]), "r"(b[1]));
}

// ============================================================================
// Kernel 1: QKV GEMM.  C[32768,1536] = x[32768,512] @ W_qkv[512,1536]
// Epilogue scatters into g_Q/g_K/g_V laid out [b,h,n,d].
// Block tile 128x128, K-tile 32. 256 threads = 8 warps (2 M x 4 N), warp 64x32.
// ============================================================================
__global__ __launch_bounds__(256) void qkv_gemm_kernel(
    const float* __restrict__ A, const float* __restrict__ W)
{
    __shared__ float As[128*36];   // stride 36 (== 4 mod 32): conflict-free A frags
    __shared__ float Bs[32*136];   // stride 136 (== 8 mod 32): conflict-free B frags
    const int tid = threadIdx.x, lane = tid & 31, w = tid >> 5;
    const int gr = lane >> 2, gc = lane & 3;
    const int wm = w & 1, wn = w >> 1;
    const int mBase = blockIdx.y * 128, nBase = blockIdx.x * 128;

    float acc[4][4][4];
    #pragma unroll
    for (int i=0;i<4;i++)
        #pragma unroll
        for (int j=0;j<4;j++)
            #pragma unroll
            for (int c=0;c<4;c++) acc[i][j][c] = 0.f;

    for (int kt = 0; kt < 512; kt += 32){
        #pragma unroll
        for (int ii = 0; ii < 4; ii++){
            int i = tid + ii*256;
            int r = i >> 3, c = (i & 7) << 2;
            float4 v = *(const float4*)(A + (size_t)(mBase + r)*512 + kt + c);
            float* p = As + r*36 + c;
            p[0]=tf32r(v.x); p[1]=tf32r(v.y); p[2]=tf32r(v.z); p[3]=tf32r(v.w);
        }
        #pragma unroll
        for (int ii = 0; ii < 4; ii++){
            int i = tid + ii*256;
            int r = i >> 5, c = (i & 31) << 2;
            float4 v = *(const float4*)(W + (size_t)(kt + r)*1536 + nBase + c);
            float* p = Bs + r*136 + c;
            p[0]=tf32r(v.x); p[1]=tf32r(v.y); p[2]=tf32r(v.z); p[3]=tf32r(v.w);
        }
        __syncthreads();
        #pragma unroll
        for (int ks = 0; ks < 4; ks++){
            int kb = ks*8;
            unsigned a[4][4], bb[4][2];
            #pragma unroll
            for (int mt=0; mt<4; mt++){
                int r0 = wm*64 + mt*16;
                a[mt][0]=fu(As[(r0+gr   )*36 + kb+gc  ]);
                a[mt][1]=fu(As[(r0+gr+8 )*36 + kb+gc  ]);
                a[mt][2]=fu(As[(r0+gr   )*36 + kb+gc+4]);
                a[mt][3]=fu(As[(r0+gr+8 )*36 + kb+gc+4]);
            }
            #pragma unroll
            for (int nt=0; nt<4; nt++){
                int n0 = wn*32 + nt*8;
                bb[nt][0]=fu(Bs[(kb+gc  )*136 + n0+gr]);
                bb[nt][1]=fu(Bs[(kb+gc+4)*136 + n0+gr]);
            }
            #pragma unroll
            for (int mt=0; mt<4; mt++)
                #pragma unroll
                for (int nt=0; nt<4; nt++)
                    mma8(acc[mt][nt], a[mt], bb[nt]);
        }
        __syncthreads();
    }
    // epilogue: scatter into Q/K/V [b,h,n,d]
    #pragma unroll
    for (int mt=0; mt<4; mt++){
        #pragma unroll
        for (int nt=0; nt<4; nt++){
            int row = mBase + wm*64 + mt*16 + gr;
            int col = nBase + wn*32 + nt*8 + 2*gc;
            int p   = col >> 9;
            int rem = col & 511;
            int h   = rem >> 6, d = rem & 63;
            float* dst = (p==0 ? g_Q : (p==1 ? g_K : g_V));
            #pragma unroll
            for (int rr=0; rr<2; rr++){
                int r = row + rr*8;
                int b = r >> 10, n = r & 1023;
                float2 v = make_float2(acc[mt][nt][rr*2], acc[mt][nt][rr*2+1]);
                *(float2*)(dst + ((size_t)((b*8+h)*1024 + n))*64 + d) = v;
            }
        }
    }
}

// ============================================================================
// Kernel 2: attention.  One block per (b, h, 128-row tile). 256 threads.
// Flash-style online softmax; decay mask applied to numerator only.
// ============================================================================
#define QS 68     // Q/K smem stride (== 4 mod 32)
#define VS 72     // V smem stride (== 8 mod 32)
#define PS 132    // P smem stride (== 4 mod 32)
#define ATT_SMEM ((128*QS + 128*QS + 128*VS + 128*PS)*4)

__global__ __launch_bounds__(256) void attn_kernel(const float* __restrict__ mask)
{
    extern __shared__ float sm[];
    float* Qs = sm;
    float* Ks = Qs + 128*QS;
    float* Vs = Ks + 128*QS;
    float* Ps = Vs + 128*VS;

    const int tid = threadIdx.x, lane = tid & 31, w = tid >> 5;
    const int gr = lane >> 2, gc = lane & 3;
    const int b = blockIdx.z, h = blockIdx.y, rt = blockIdx.x;
    const int r0 = w * 16;   // each warp owns 16 rows

    const float* Qg = g_Q + ((size_t)((b*8+h)*1024 + rt*128))*64;
    const float* Kg = g_K + ((size_t)((b*8+h)*1024))*64;
    const float* Vg = g_V + ((size_t)((b*8+h)*1024))*64;
    const float* Mg = mask + ((size_t)(h*1024 + rt*128))*1024;

    #pragma unroll
    for (int ii = 0; ii < 8; ii++){
        int i = tid + ii*256;
        int r = i >> 4, c = (i & 15) << 2;
        float4 v = *(const float4*)(Qg + r*64 + c);
        float* p = Qs + r*QS + c;
        p[0]=tf32r(v.x); p[1]=tf32r(v.y); p[2]=tf32r(v.z); p[3]=tf32r(v.w);
    }

    float o[8][4];
    #pragma unroll
    for (int i=0;i<8;i++){ o[i][0]=0.f;o[i][1]=0.f;o[i][2]=0.f;o[i][3]=0.f; }
    float mrow0 = -1e30f, mrow1 = -1e30f, lrow0 = 0.f, lrow1 = 0.f;

    for (int jt = 0; jt < 8; jt++){
        const float* kp = Kg + jt*128*64;
        const float* vp = Vg + jt*128*64;
        #pragma unroll
        for (int ii = 0; ii < 8; ii++){
            int i = tid + ii*256;
            int r = i >> 4, c = (i & 15) << 2;
            float4 vk = *(const float4*)(kp + r*64 + c);
            float* p = Ks + r*QS + c;
            p[0]=tf32r(vk.x); p[1]=tf32r(vk.y); p[2]=tf32r(vk.z); p[3]=tf32r(vk.w);
            float4 vv = *(const float4*)(vp + r*64 + c);
            float* q = Vs + r*VS + c;
            q[0]=tf32r(vv.x); q[1]=tf32r(vv.y); q[2]=tf32r(vv.z); q[3]=tf32r(vv.w);
        }
        __syncthreads();

        // S = Q K^T : warp's 16 rows x 128 cols
        float s[16][4];
        #pragma unroll
        for (int i=0;i<16;i++){ s[i][0]=0.f;s[i][1]=0.f;s[i][2]=0.f;s[i][3]=0.f; }
        #pragma unroll
        for (int ks=0; ks<8; ks++){
            int kb = ks*8;
            unsigned a[4] = {
                fu(Qs[(r0+gr  )*QS + kb+gc  ]),
                fu(Qs[(r0+gr+8)*QS + kb+gc  ]),
                fu(Qs[(r0+gr  )*QS + kb+gc+4]),
                fu(Qs[(r0+gr+8)*QS + kb+gc+4]) };
            #pragma unroll
            for (int nt=0; nt<16; nt++){
                int n0 = nt*8;
                unsigned bb[2] = {
                    fu(Ks[(n0+gr)*QS + kb+gc  ]),
                    fu(Ks[(n0+gr)*QS + kb+gc+4]) };
                mma8(s[nt], a, bb);
            }
        }

        // scale + online softmax state
        float ml0 = -1e30f, ml1 = -1e30f;
        #pragma unroll
        for (int nt=0; nt<16; nt++){
            s[nt][0]*=SCALE; s[nt][1]*=SCALE; s[nt][2]*=SCALE; s[nt][3]*=SCALE;
            ml0 = fmaxf(ml0, fmaxf(s[nt][0], s[nt][1]));
            ml1 = fmaxf(ml1, fmaxf(s[nt][2], s[nt][3]));
        }
        ml0 = fmaxf(ml0, __shfl_xor_sync(0xffffffffu, ml0, 1));
        ml0 = fmaxf(ml0, __shfl_xor_sync(0xffffffffu, ml0, 2));
        ml1 = fmaxf(ml1, __shfl_xor_sync(0xffffffffu, ml1, 1));
        ml1 = fmaxf(ml1, __shfl_xor_sync(0xffffffffu, ml1, 2));
        float mn0 = fmaxf(mrow0, ml0), mn1 = fmaxf(mrow1, ml1);
        float al0 = __expf(mrow0 - mn0), al1 = __expf(mrow1 - mn1);
        mrow0 = mn0; mrow1 = mn1;

        float ls0 = 0.f, ls1 = 0.f;
        const float* mrp0 = Mg + (size_t)(r0+gr  )*1024 + jt*128;
        const float* mrp1 = Mg + (size_t)(r0+gr+8)*1024 + jt*128;
        #pragma unroll
        for (int nt=0; nt<16; nt++){
            int cc = nt*8 + 2*gc;
            float e0 = __expf(s[nt][0]-mn0), e1 = __expf(s[nt][1]-mn0);
            float e2 = __expf(s[nt][2]-mn1), e3 = __expf(s[nt][3]-mn1);
            ls0 += e0 + e1; ls1 += e2 + e3;
            float2 mk0 = *(const float2*)(mrp0 + cc);
            float2 mk1 = *(const float2*)(mrp1 + cc);
            float* pp0 = Ps + (r0+gr)*PS + cc;
            pp0[0] = tf32r(e0*mk0.x); pp0[1] = tf32r(e1*mk0.y);
            float* pp1 = Ps + (r0+gr+8)*PS + cc;
            pp1[0] = tf32r(e2*mk1.x); pp1[1] = tf32r(e3*mk1.y);
        }
        lrow0 = lrow0*al0 + ls0;
        lrow1 = lrow1*al1 + ls1;
        #pragma unroll
        for (int nt=0; nt<8; nt++){
            o[nt][0]*=al0; o[nt][1]*=al0; o[nt][2]*=al1; o[nt][3]*=al1;
        }
        __syncwarp();   // Ps rows are warp-private: warp-level ordering suffices

        // O += P @ V : warp's 16 rows x 64 d-cols, k = 128
        #pragma unroll
        for (int ks=0; ks<16; ks++){
            int kb = ks*8;
            unsigned a[4] = {
                fu(Ps[(r0+gr  )*PS + kb+gc  ]),
                fu(Ps[(r0+gr+8)*PS + kb+gc  ]),
                fu(Ps[(r0+gr  )*PS + kb+gc+4]),
                fu(Ps[(r0+gr+8)*PS + kb+gc+4]) };
            #pragma unroll
            for (int nt=0; nt<8; nt++){
                int n0 = nt*8;
                unsigned bb[2] = {
                    fu(Vs[(kb+gc  )*VS + n0+gr]),
                    fu(Vs[(kb+gc+4)*VS + n0+gr]) };
                mma8(o[nt], a, bb);
            }
        }
        __syncthreads();   // before next iteration overwrites Ks/Vs
    }

    // finalize: full row-sum across the 4 lanes sharing each row, then divide
    lrow0 += __shfl_xor_sync(0xffffffffu, lrow0, 1);
    lrow0 += __shfl_xor_sync(0xffffffffu, lrow0, 2);
    lrow1 += __shfl_xor_sync(0xffffffffu, lrow1, 1);
    lrow1 += __shfl_xor_sync(0xffffffffu, lrow1, 2);
    float inv0 = 1.f / lrow0, inv1 = 1.f / lrow1;

    float* Og = g_O + ((size_t)(b*1024 + rt*128))*512 + h*64;
    #pragma unroll
    for (int nt=0; nt<8; nt++){
        int d = nt*8 + 2*gc;
        *(float2*)(Og + (size_t)(r0+gr  )*512 + d) =
            make_float2(o[nt][0]*inv0, o[nt][1]*inv0);
        *(float2*)(Og + (size_t)(r0+gr+8)*512 + d) =
            make_float2(o[nt][2]*inv1, o[nt][3]*inv1);
    }
}

// ============================================================================
// Kernel 3: out = g_O[32768,512] @ W_out[512,512] + b_out
// ============================================================================
__global__ __launch_bounds__(256) void out_gemm_kernel(
    const float* __restrict__ W, const float* __restrict__ bias,
    float* __restrict__ out)
{
    __shared__ float As[128*36];
    __shared__ float Bs[32*136];
    const int tid = threadIdx.x, lane = tid & 31, w = tid >> 5;
    const int gr = lane >> 2, gc = lane & 3;
    const int wm = w & 1, wn = w >> 1;
    const int mBase = blockIdx.y * 128, nBase = blockIdx.x * 128;

    float acc[4][4][4];
    #pragma unroll
    for (int i=0;i<4;i++)
        #pragma unroll
        for (int j=0;j<4;j++)
            #pragma unroll
            for (int c=0;c<4;c++) acc[i][j][c] = 0.f;

    for (int kt = 0; kt < 512; kt += 32){
        #pragma unroll
        for (int ii = 0; ii < 4; ii++){
            int i = tid + ii*256;
            int r = i >> 3, c = (i & 7) << 2;
            float4 v = *(const float4*)(g_O + (size_t)(mBase + r)*512 + kt + c);
            float* p = As + r*36 + c;
            p[0]=tf32r(v.x); p[1]=tf32r(v.y); p[2]=tf32r(v.z); p[3]=tf32r(v.w);
        }
        #pragma unroll
        for (int ii = 0; ii < 4; ii++){
            int i = tid + ii*256;
            int r = i >> 5, c = (i & 31) << 2;
            float4 v = *(const float4*)(W + (size_t)(kt + r)*512 + nBase + c);
            float* p = Bs + r*136 + c;
            p[0]=tf32r(v.x); p[1]=tf32r(v.y); p[2]=tf32r(v.z); p[3]=tf32r(v.w);
        }
        __syncthreads();
        #pragma unroll
        for (int ks = 0; ks < 4; ks++){
            int kb = ks*8;
            unsigned a[4][4], bb[4][2];
            #pragma unroll
            for (int mt=0; mt<4; mt++){
                int r0 = wm*64 + mt*16;
                a[mt][0]=fu(As[(r0+gr   )*36 + kb+gc  ]);
                a[mt][1]=fu(As[(r0+gr+8 )*36 + kb+gc  ]);
                a[mt][2]=fu(As[(r0+gr   )*36 + kb+gc+4]);
                a[mt][3]=fu(As[(r0+gr+8 )*36 + kb+gc+4]);
            }
            #pragma unroll
            for (int nt=0; nt<4; nt++){
                int n0 = wn*32 + nt*8;
                bb[nt][0]=fu(Bs[(kb+gc  )*136 + n0+gr]);
                bb[nt][1]=fu(Bs[(kb+gc+4)*136 + n0+gr]);
            }
            #pragma unroll
            for (int mt=0; mt<4; mt++)
                #pragma unroll
                for (int nt=0; nt<4; nt++)
                    mma8(acc[mt][nt], a[mt], bb[nt]);
        }
        __syncthreads();
    }
    #pragma unroll
    for (int mt=0; mt<4; mt++){
        #pragma unroll
        for (int nt=0; nt<4; nt++){
            int row = mBase + wm*64 + mt*16 + gr;
            int col = nBase + wn*32 + nt*8 + 2*gc;
            float b0 = bias[col], b1 = bias[col+1];
            *(float2*)(out + (size_t)row*512 + col) =
                make_float2(acc[mt][nt][0] + b0, acc[mt][nt][1] + b1);
            *(float2*)(out + (size_t)(row+8)*512 + col) =
                make_float2(acc[mt][nt][2] + b0, acc[mt][nt][3] + b1);
        }
    }
}

// ============================================================================
extern "C" void kernel_launch(void* const* d_in, const int* in_sizes, int n_in,
                              void* d_out, int out_size)
{
    (void)in_sizes; (void)n_in; (void)out_size;
    const float* x    = (const float*)d_in[0];
    const float* Wqkv = (const float*)d_in[1];
    const float* Wout = (const float*)d_in[2];
    const float* bout = (const float*)d_in[3];
    const float* mask = (const float*)d_in[4];
    float* out = (float*)d_out;

    cudaFuncSetAttribute(attn_kernel,
                         cudaFuncAttributeMaxDynamicSharedMemorySize, ATT_SMEM);

    qkv_gemm_kernel<<<dim3(12, 256), 256>>>(x, Wqkv);
    attn_kernel<<<dim3(8, 8, 32), 256, ATT_SMEM>>>(mask);
    out_gemm_kernel<<<dim3(4, 256), 256>>>(Wout, bout, out);
}

// round 4
// speedup vs baseline: 1.0424x; 1.0424x over previous
#include <cuda_runtime.h>
#include <cstdint>
#include <cstddef>

#define Bb 32
#define Nn 1024
#define DIM 512
#define Hh 8
#define DHd 64
#define SCALE 0.125f

// Scratch (device globals: allocation-free per harness rules)
__device__ float g_Q[Bb*Hh*Nn*DHd];   // [b,h,n,d]
__device__ float g_K[Bb*Hh*Nn*DHd];
__device__ float g_V[Bb*Hh*Nn*DHd];
__device__ float g_O[Bb*Nn*Hh*DHd];   // [b,n,h*64+d]

__device__ __forceinline__ float tf32r(float x){
    unsigned r; asm("cvt.rna.tf32.f32 %0, %1;" : "=r"(r) : "f"(x));
    return __uint_as_float(r);
}
__device__ __forceinline__ unsigned fu(float x){ return __float_as_uint(x); }

// D += A(16x8,row) * B(8x8,col)  tf32
__device__ __forceinline__ void mma8(float* d, const unsigned* a, const unsigned* b){
    asm volatile(
        "mma.sync.aligned.m16n8k8.row.col.f32.tf32.tf32.f32 "
        "{%0,%1,%2,%3},{%4,%5,%6,%7},{%8,%9},{%0,%1,%2,%3};\n"
        : "+f"(d[0]), "+f"(d[1]), "+f"(d[2]), "+f"(d[3])
        : "r"(a[0]), "r"(a[1]), "r"(a[2]), "r"(a[3]), "r"(b[0]), "r"(b[1]));
}

// ============================================================================
// Kernel 1: QKV GEMM.  C[32768,1536] = x[32768,512] @ W_qkv[512,1536]
// Epilogue scatters into g_Q/g_K/g_V laid out [b,h,n,d].
// Block tile 128x128, K-tile 32. 256 threads = 8 warps (2 M x 4 N), warp 64x32.
// ============================================================================
__global__ __launch_bounds__(256) void qkv_gemm_kernel(
    const float* __restrict__ A, const float* __restrict__ W)
{
    __shared__ float As[128*36];   // stride 36 (== 4 mod 32): conflict-free A frags
    __shared__ float Bs[32*136];   // stride 136 (== 8 mod 32): conflict-free B frags
    const int tid = threadIdx.x, lane = tid & 31, w = tid >> 5;
    const int gr = lane >> 2, gc = lane & 3;
    const int wm = w & 1, wn = w >> 1;
    const int mBase = blockIdx.y * 128, nBase = blockIdx.x * 128;

    float acc[4][4][4];
    #pragma unroll
    for (int i=0;i<4;i++)
        #pragma unroll
        for (int j=0;j<4;j++)
            #pragma unroll
            for (int c=0;c<4;c++) acc[i][j][c] = 0.f;

    for (int kt = 0; kt < 512; kt += 32){
        #pragma unroll
        for (int ii = 0; ii < 4; ii++){
            int i = tid + ii*256;
            int r = i >> 3, c = (i & 7) << 2;
            float4 v = *(const float4*)(A + (size_t)(mBase + r)*512 + kt + c);
            float* p = As + r*36 + c;
            p[0]=tf32r(v.x); p[1]=tf32r(v.y); p[2]=tf32r(v.z); p[3]=tf32r(v.w);
        }
        #pragma unroll
        for (int ii = 0; ii < 4; ii++){
            int i = tid + ii*256;
            int r = i >> 5, c = (i & 31) << 2;
            float4 v = *(const float4*)(W + (size_t)(kt + r)*1536 + nBase + c);
            float* p = Bs + r*136 + c;
            p[0]=tf32r(v.x); p[1]=tf32r(v.y); p[2]=tf32r(v.z); p[3]=tf32r(v.w);
        }
        __syncthreads();
        #pragma unroll
        for (int ks = 0; ks < 4; ks++){
            int kb = ks*8;
            unsigned a[4][4], bb[4][2];
            #pragma unroll
            for (int mt=0; mt<4; mt++){
                int r0 = wm*64 + mt*16;
                a[mt][0]=fu(As[(r0+gr   )*36 + kb+gc  ]);
                a[mt][1]=fu(As[(r0+gr+8 )*36 + kb+gc  ]);
                a[mt][2]=fu(As[(r0+gr   )*36 + kb+gc+4]);
                a[mt][3]=fu(As[(r0+gr+8 )*36 + kb+gc+4]);
            }
            #pragma unroll
            for (int nt=0; nt<4; nt++){
                int n0 = wn*32 + nt*8;
                bb[nt][0]=fu(Bs[(kb+gc  )*136 + n0+gr]);
                bb[nt][1]=fu(Bs[(kb+gc+4)*136 + n0+gr]);
            }
            #pragma unroll
            for (int mt=0; mt<4; mt++)
                #pragma unroll
                for (int nt=0; nt<4; nt++)
                    mma8(acc[mt][nt], a[mt], bb[nt]);
        }
        __syncthreads();
    }
    // epilogue: scatter into Q/K/V [b,h,n,d]
    #pragma unroll
    for (int mt=0; mt<4; mt++){
        #pragma unroll
        for (int nt=0; nt<4; nt++){
            int row = mBase + wm*64 + mt*16 + gr;
            int col = nBase + wn*32 + nt*8 + 2*gc;
            int p   = col >> 9;
            int rem = col & 511;
            int h   = rem >> 6, d = rem & 63;
            float* dst = (p==0 ? g_Q : (p==1 ? g_K : g_V));
            #pragma unroll
            for (int rr=0; rr<2; rr++){
                int r = row + rr*8;
                int b = r >> 10, n = r & 1023;
                float2 v = make_float2(acc[mt][nt][rr*2], acc[mt][nt][rr*2+1]);
                *(float2*)(dst + ((size_t)((b*8+h)*1024 + n))*64 + d) = v;
            }
        }
    }
}

// ============================================================================
// Kernel 2: attention.  One block per (b, h, 128-row tile). 256 threads.
// Flash-style online softmax over 64-column j-chunks (16 iterations).
// Smem 103KB -> 2 CTAs/SM, single wave of 256 CTAs.
// ============================================================================
#define QS 68     // Q/K smem stride (== 4 mod 32)
#define VS 72     // V smem stride (== 8 mod 32)
#define PS 68     // P smem stride (== 4 mod 32)
#define ATT_SMEM ((128*QS + 64*QS + 64*VS + 128*PS)*4)

__global__ __launch_bounds__(256, 2) void attn_kernel(const float* __restrict__ mask)
{
    extern __shared__ float sm[];
    float* Qs = sm;                 // 128 x 64 (stride QS)
    float* Ks = Qs + 128*QS;        //  64 x 64 (stride QS)
    float* Vs = Ks + 64*QS;         //  64 x 64 (stride VS)
    float* Ps = Vs + 64*VS;         // 128 x 64 (stride PS)

    const int tid = threadIdx.x, lane = tid & 31, w = tid >> 5;
    const int gr = lane >> 2, gc = lane & 3;
    const int b = blockIdx.z, h = blockIdx.y, rt = blockIdx.x;
    const int r0 = w * 16;   // each warp owns 16 q-rows

    const float* Qg = g_Q + ((size_t)((b*8+h)*1024 + rt*128))*64;
    const float* Kg = g_K + ((size_t)((b*8+h)*1024))*64;
    const float* Vg = g_V + ((size_t)((b*8+h)*1024))*64;
    const float* Mg = mask + ((size_t)(h*1024 + rt*128))*1024;

    // Q tile: 128 x 64, tf32-rounded
    #pragma unroll
    for (int ii = 0; ii < 8; ii++){
        int i = tid + ii*256;
        int r = i >> 4, c = (i & 15) << 2;
        float4 v = *(const float4*)(Qg + r*64 + c);
        float* p = Qs + r*QS + c;
        p[0]=tf32r(v.x); p[1]=tf32r(v.y); p[2]=tf32r(v.z); p[3]=tf32r(v.w);
    }

    float o[8][4];
    #pragma unroll
    for (int i=0;i<8;i++){ o[i][0]=0.f;o[i][1]=0.f;o[i][2]=0.f;o[i][3]=0.f; }
    float mrow0 = -1e30f, mrow1 = -1e30f, lrow0 = 0.f, lrow1 = 0.f;

    for (int jt = 0; jt < 16; jt++){       // 64-col chunks
        const float* kp = Kg + jt*64*64;
        const float* vp = Vg + jt*64*64;
        // load K,V chunk: 64x64 each (1024 float4 each; 4/thread)
        #pragma unroll
        for (int ii = 0; ii < 4; ii++){
            int i = tid + ii*256;
            int r = i >> 4, c = (i & 15) << 2;
            float4 vk = *(const float4*)(kp + r*64 + c);
            float* p = Ks + r*QS + c;
            p[0]=tf32r(vk.x); p[1]=tf32r(vk.y); p[2]=tf32r(vk.z); p[3]=tf32r(vk.w);
            float4 vv = *(const float4*)(vp + r*64 + c);
            float* q = Vs + r*VS + c;
            q[0]=tf32r(vv.x); q[1]=tf32r(vv.y); q[2]=tf32r(vv.z); q[3]=tf32r(vv.w);
        }
        __syncthreads();

        // S = Q K^T : warp's 16 rows x 64 cols
        float s[8][4];
        #pragma unroll
        for (int i=0;i<8;i++){ s[i][0]=0.f;s[i][1]=0.f;s[i][2]=0.f;s[i][3]=0.f; }
        #pragma unroll
        for (int ks=0; ks<8; ks++){
            int kb = ks*8;
            unsigned a[4] = {
                fu(Qs[(r0+gr  )*QS + kb+gc  ]),
                fu(Qs[(r0+gr+8)*QS + kb+gc  ]),
                fu(Qs[(r0+gr  )*QS + kb+gc+4]),
                fu(Qs[(r0+gr+8)*QS + kb+gc+4]) };
            #pragma unroll
            for (int nt=0; nt<8; nt++){
                int n0 = nt*8;
                unsigned bb[2] = {
                    fu(Ks[(n0+gr)*QS + kb+gc  ]),
                    fu(Ks[(n0+gr)*QS + kb+gc+4]) };
                mma8(s[nt], a, bb);
            }
        }

        // scale + online softmax state
        float ml0 = -1e30f, ml1 = -1e30f;
        #pragma unroll
        for (int nt=0; nt<8; nt++){
            s[nt][0]*=SCALE; s[nt][1]*=SCALE; s[nt][2]*=SCALE; s[nt][3]*=SCALE;
            ml0 = fmaxf(ml0, fmaxf(s[nt][0], s[nt][1]));
            ml1 = fmaxf(ml1, fmaxf(s[nt][2], s[nt][3]));
        }
        ml0 = fmaxf(ml0, __shfl_xor_sync(0xffffffffu, ml0, 1));
        ml0 = fmaxf(ml0, __shfl_xor_sync(0xffffffffu, ml0, 2));
        ml1 = fmaxf(ml1, __shfl_xor_sync(0xffffffffu, ml1, 1));
        ml1 = fmaxf(ml1, __shfl_xor_sync(0xffffffffu, ml1, 2));
        float mn0 = fmaxf(mrow0, ml0), mn1 = fmaxf(mrow1, ml1);
        float al0 = __expf(mrow0 - mn0), al1 = __expf(mrow1 - mn1);
        mrow0 = mn0; mrow1 = mn1;

        float ls0 = 0.f, ls1 = 0.f;
        const float* mrp0 = Mg + (size_t)(r0+gr  )*1024 + jt*64;
        const float* mrp1 = Mg + (size_t)(r0+gr+8)*1024 + jt*64;
        #pragma unroll
        for (int nt=0; nt<8; nt++){
            int cc = nt*8 + 2*gc;
            float e0 = __expf(s[nt][0]-mn0), e1 = __expf(s[nt][1]-mn0);
            float e2 = __expf(s[nt][2]-mn1), e3 = __expf(s[nt][3]-mn1);
            ls0 += e0 + e1; ls1 += e2 + e3;
            float2 mk0 = *(const float2*)(mrp0 + cc);
            float2 mk1 = *(const float2*)(mrp1 + cc);
            *(float2*)(Ps + (r0+gr  )*PS + cc) =
                make_float2(tf32r(e0*mk0.x), tf32r(e1*mk0.y));
            *(float2*)(Ps + (r0+gr+8)*PS + cc) =
                make_float2(tf32r(e2*mk1.x), tf32r(e3*mk1.y));
        }
        lrow0 = lrow0*al0 + ls0;
        lrow1 = lrow1*al1 + ls1;
        #pragma unroll
        for (int nt=0; nt<8; nt++){
            o[nt][0]*=al0; o[nt][1]*=al0; o[nt][2]*=al1; o[nt][3]*=al1;
        }
        __syncwarp();   // Ps rows are warp-private: warp-level ordering suffices

        // O += P @ V : warp's 16 rows x 64 d-cols, k = 64
        #pragma unroll
        for (int ks=0; ks<8; ks++){
            int kb = ks*8;
            unsigned a[4] = {
                fu(Ps[(r0+gr  )*PS + kb+gc  ]),
                fu(Ps[(r0+gr+8)*PS + kb+gc  ]),
                fu(Ps[(r0+gr  )*PS + kb+gc+4]),
                fu(Ps[(r0+gr+8)*PS + kb+gc+4]) };
            #pragma unroll
            for (int nt=0; nt<8; nt++){
                int n0 = nt*8;
                unsigned bb[2] = {
                    fu(Vs[(kb+gc  )*VS + n0+gr]),
                    fu(Vs[(kb+gc+4)*VS + n0+gr]) };
                mma8(o[nt], a, bb);
            }
        }
        __syncthreads();   // before next iteration overwrites Ks/Vs
    }

    // finalize: full row-sum across the 4 lanes sharing each row, then divide
    lrow0 += __shfl_xor_sync(0xffffffffu, lrow0, 1);
    lrow0 += __shfl_xor_sync(0xffffffffu, lrow0, 2);
    lrow1 += __shfl_xor_sync(0xffffffffu, lrow1, 1);
    lrow1 += __shfl_xor_sync(0xffffffffu, lrow1, 2);
    float inv0 = 1.f / lrow0, inv1 = 1.f / lrow1;

    float* Og = g_O + ((size_t)(b*1024 + rt*128))*512 + h*64;
    #pragma unroll
    for (int nt=0; nt<8; nt++){
        int d = nt*8 + 2*gc;
        *(float2*)(Og + (size_t)(r0+gr  )*512 + d) =
            make_float2(o[nt][0]*inv0, o[nt][1]*inv0);
        *(float2*)(Og + (size_t)(r0+gr+8)*512 + d) =
            make_float2(o[nt][2]*inv1, o[nt][3]*inv1);
    }
}

// ============================================================================
// Kernel 3: out = g_O[32768,512] @ W_out[512,512] + b_out
// ============================================================================
__global__ __launch_bounds__(256) void out_gemm_kernel(
    const float* __restrict__ W, const float* __restrict__ bias,
    float* __restrict__ out)
{
    __shared__ float As[128*36];
    __shared__ float Bs[32*136];
    const int tid = threadIdx.x, lane = tid & 31, w = tid >> 5;
    const int gr = lane >> 2, gc = lane & 3;
    const int wm = w & 1, wn = w >> 1;
    const int mBase = blockIdx.y * 128, nBase = blockIdx.x * 128;

    float acc[4][4][4];
    #pragma unroll
    for (int i=0;i<4;i++)
        #pragma unroll
        for (int j=0;j<4;j++)
            #pragma unroll
            for (int c=0;c<4;c++) acc[i][j][c] = 0.f;

    for (int kt = 0; kt < 512; kt += 32){
        #pragma unroll
        for (int ii = 0; ii < 4; ii++){
            int i = tid + ii*256;
            int r = i >> 3, c = (i & 7) << 2;
            float4 v = *(const float4*)(g_O + (size_t)(mBase + r)*512 + kt + c);
            float* p = As + r*36 + c;
            p[0]=tf32r(v.x); p[1]=tf32r(v.y); p[2]=tf32r(v.z); p[3]=tf32r(v.w);
        }
        #pragma unroll
        for (int ii = 0; ii < 4; ii++){
            int i = tid + ii*256;
            int r = i >> 5, c = (i & 31) << 2;
            float4 v = *(const float4*)(W + (size_t)(kt + r)*512 + nBase + c);
            float* p = Bs + r*136 + c;
            p[0]=tf32r(v.x); p[1]=tf32r(v.y); p[2]=tf32r(v.z); p[3]=tf32r(v.w);
        }
        __syncthreads();
        #pragma unroll
        for (int ks = 0; ks < 4; ks++){
            int kb = ks*8;
            unsigned a[4][4], bb[4][2];
            #pragma unroll
            for (int mt=0; mt<4; mt++){
                int r0 = wm*64 + mt*16;
                a[mt][0]=fu(As[(r0+gr   )*36 + kb+gc  ]);
                a[mt][1]=fu(As[(r0+gr+8 )*36 + kb+gc  ]);
                a[mt][2]=fu(As[(r0+gr   )*36 + kb+gc+4]);
                a[mt][3]=fu(As[(r0+gr+8 )*36 + kb+gc+4]);
            }
            #pragma unroll
            for (int nt=0; nt<4; nt++){
                int n0 = wn*32 + nt*8;
                bb[nt][0]=fu(Bs[(kb+gc  )*136 + n0+gr]);
                bb[nt][1]=fu(Bs[(kb+gc+4)*136 + n0+gr]);
            }
            #pragma unroll
            for (int mt=0; mt<4; mt++)
                #pragma unroll
                for (int nt=0; nt<4; nt++)
                    mma8(acc[mt][nt], a[mt], bb[nt]);
        }
        __syncthreads();
    }
    #pragma unroll
    for (int mt=0; mt<4; mt++){
        #pragma unroll
        for (int nt=0; nt<4; nt++){
            int row = mBase + wm*64 + mt*16 + gr;
            int col = nBase + wn*32 + nt*8 + 2*gc;
            float b0 = bias[col], b1 = bias[col+1];
            *(float2*)(out + (size_t)row*512 + col) =
                make_float2(acc[mt][nt][0] + b0, acc[mt][nt][1] + b1);
            *(float2*)(out + (size_t)(row+8)*512 + col) =
                make_float2(acc[mt][nt][2] + b0, acc[mt][nt][3] + b1);
        }
    }
}

// ============================================================================
extern "C" void kernel_launch(void* const* d_in, const int* in_sizes, int n_in,
                              void* d_out, int out_size)
{
    (void)in_sizes; (void)n_in; (void)out_size;
    const float* x    = (const float*)d_in[0];
    const float* Wqkv = (const float*)d_in[1];
    const float* Wout = (const float*)d_in[2];
    const float* bout = (const float*)d_in[3];
    const float* mask = (const float*)d_in[4];
    float* out = (float*)d_out;

    cudaFuncSetAttribute(attn_kernel,
                         cudaFuncAttributeMaxDynamicSharedMemorySize, ATT_SMEM);

    qkv_gemm_kernel<<<dim3(12, 256), 256>>>(x, Wqkv);
    attn_kernel<<<dim3(8, 8, 32), 256, ATT_SMEM>>>(mask);
    out_gemm_kernel<<<dim3(4, 256), 256>>>(Wout, bout, out);
}